// round 2
// baseline (speedup 1.0000x reference)
#include <cuda_runtime.h>

#define NB       262144
#define THREADS  256
#define NTILES   (NB / THREADS)   // 1024
#define GRID_X   148

typedef unsigned long long u64;

// ---- packed f32x2 helpers (SASS FFMA2 path) ----
__device__ __forceinline__ u64 ffma2(u64 a, u64 b, u64 c) {
    u64 d;
    asm("fma.rn.f32x2 %0, %1, %2, %3;" : "=l"(d) : "l"(a), "l"(b), "l"(c));
    return d;
}
__device__ __forceinline__ u64 fadd2(u64 a, u64 b) {
    u64 d;
    asm("add.rn.f32x2 %0, %1, %2;" : "=l"(d) : "l"(a), "l"(b));
    return d;
}
__device__ __forceinline__ u64 pack2(float lo, float hi) {
    u64 d;
    asm("mov.b64 %0, {%1, %2};" : "=l"(d) : "f"(lo), "f"(hi));
    return d;
}
__device__ __forceinline__ void unpack2(u64 a, float& lo, float& hi) {
    asm("mov.b64 {%0, %1}, %2;" : "=f"(lo), "=f"(hi) : "l"(a));
}
__device__ __forceinline__ float hsum2(u64 a) {
    float lo, hi; unpack2(a, lo, hi); return lo + hi;
}

// backward dot: one 64-float transposed-weight row (smem broadcast LDS.128)
// with packed reg vector v. Order-free (values only).
__device__ __forceinline__ float dot64(const float* __restrict__ Wrow, const u64 (&v)[32]) {
    const ulonglong2* wr = reinterpret_cast<const ulonglong2*>(Wrow);
    u64 A = 0ull, B = 0ull, C = 0ull, D = 0ull;
#pragma unroll
    for (int i = 0; i < 16; i += 4) {
        ulonglong2 w0 = wr[i + 0];
        ulonglong2 w1 = wr[i + 1];
        ulonglong2 w2 = wr[i + 2];
        ulonglong2 w3 = wr[i + 3];
        A = ffma2(w0.x, v[2*i + 0], A);
        B = ffma2(w0.y, v[2*i + 1], B);
        C = ffma2(w1.x, v[2*i + 2], C);
        D = ffma2(w1.y, v[2*i + 3], D);
        A = ffma2(w2.x, v[2*i + 4], A);
        B = ffma2(w2.y, v[2*i + 5], B);
        C = ffma2(w3.x, v[2*i + 6], C);
        D = ffma2(w3.y, v[2*i + 7], D);
    }
    return hsum2(fadd2(fadd2(A, B), fadd2(C, D)));
}

// ---- smem layout (bytes) ----
// [0)        u64 Wf[3][64][32]   packed forward pairs: {W[2p][k+1], W[2p+1][k+1]}
// [49152)    u64 Wt[3][32]       packed t-column pairs: {W[2p][0], W[2p+1][0]}
// [49920)    u64 scp[32][256]    per-thread activation scratch (pairs, transposed)
// [115456)   float Wb[3][64*64]  backward transposed: Wb[l][k*64+j] = W_l[j][k+1]
// [164608)   float Bf[3][64]     biases
#define OFF_WF   0
#define OFF_WT   (6144)          // in u64 units
#define OFF_SCP  (6240)          // in u64 units
#define OFF_WB   (115456)        // bytes
#define OFF_BF   (164608)        // bytes
#define SMEM_BYTES 165376

__global__ void __launch_bounds__(THREADS, 1)
odefunc_kernel(const float* __restrict__ t_p,
               const float* __restrict__ z,
               const float* __restrict__ e,
               const float* __restrict__ W0g, const float* __restrict__ b0g,
               const float* __restrict__ W1g, const float* __restrict__ b1g,
               const float* __restrict__ W2g, const float* __restrict__ b2g,
               float* __restrict__ out)
{
    extern __shared__ __align__(16) char smem_raw[];
    u64*   Wf  = reinterpret_cast<u64*>(smem_raw) + OFF_WF;
    u64*   Wt  = reinterpret_cast<u64*>(smem_raw) + OFF_WT;
    u64*   scp = reinterpret_cast<u64*>(smem_raw) + OFF_SCP;
    float* Wb  = reinterpret_cast<float*>(smem_raw + OFF_WB);
    float* Bf  = reinterpret_cast<float*>(smem_raw + OFF_BF);
    float* scF = reinterpret_cast<float*>(scp);

    const int tid = threadIdx.x;
    const float t = t_p[0];

    // ---- stage weights once per persistent CTA ----
    {
        float* WfF = reinterpret_cast<float*>(Wf);
        for (int idx = tid; idx < 4096; idx += THREADS) {
            int j = idx >> 6, k = idx & 63;
            float w0v = W0g[j * 65 + k + 1];
            float w1v = W1g[j * 65 + k + 1];
            float w2v = W2g[j * 65 + k + 1];
            int fi = (k * 32 + (j >> 1)) * 2 + (j & 1);   // pair-packed forward
            WfF[0 * 4096 + fi] = w0v;
            WfF[1 * 4096 + fi] = w1v;
            WfF[2 * 4096 + fi] = w2v;
            Wb[0 * 4096 + k * 64 + j] = w0v;              // transposed backward
            Wb[1 * 4096 + k * 64 + j] = w1v;
            Wb[2 * 4096 + k * 64 + j] = w2v;
        }
        float* WtF = reinterpret_cast<float*>(Wt);
        if (tid < 64) {
            WtF[0 * 64 + tid] = W0g[tid * 65];
            WtF[1 * 64 + tid] = W1g[tid * 65];
            WtF[2 * 64 + tid] = W2g[tid * 65];
            Bf[0 * 64 + tid] = b0g[tid];
            Bf[1 * 64 + tid] = b1g[tid];
            Bf[2 * 64 + tid] = b2g[tid];
        }
    }
    __syncthreads();

    const u64 tt = pack2(t, t);

    for (int tile = blockIdx.x; tile < NTILES; tile += gridDim.x) {
        const long row = (long)tile * THREADS + tid;

        // ---- stage z row into per-thread scratch column ----
        {
            const ulonglong2* zr = reinterpret_cast<const ulonglong2*>(z + row * 64);
#pragma unroll
            for (int i = 0; i < 16; ++i) {
                ulonglong2 q = zr[i];
                scp[(2 * i) * 256 + tid]     = q.x;
                scp[(2 * i + 1) * 256 + tid] = q.y;
            }
        }

        u64 m0 = 0ull, m1 = 0ull;

        // ---- forward layers: bit-exact sequential-k chains (cublas order) ----
#pragma unroll 1
        for (int layer = 0; layer < 3; ++layer) {
            const u64* WfL = Wf + layer * 2048;
            const u64* WtL = Wt + layer * 32;
            const float* bL = Bf + layer * 64;

            u64 acc[32];
#pragma unroll
            for (int p = 0; p < 32; ++p)
                acc[p] = ffma2(tt, WtL[p], 0ull);          // k=0: t * W[:,0] into 0

#pragma unroll 4
            for (int k = 0; k < 64; ++k) {                  // k ascending, serial chain
                float hk = scF[(k >> 1) * 512 + tid * 2 + (k & 1)];
                u64 hh = pack2(hk, hk);
#pragma unroll
                for (int p = 0; p < 32; ++p)
                    acc[p] = ffma2(hh, WfL[k * 32 + p], acc[p]);
            }

            if (layer == 2) {
                // linear output layer -> z_dot straight to GMEM
                u64* orow = reinterpret_cast<u64*>(out + row * 64);
#pragma unroll
                for (int p = 0; p < 32; ++p) {
                    float v0, v1; unpack2(acc[p], v0, v1);
                    v0 += bL[2 * p];  v1 += bL[2 * p + 1];   // single bias add, as ref
                    orow[p] = pack2(v0, v1);
                }
            } else {
                u64 m = 0ull;
#pragma unroll
                for (int p = 0; p < 32; ++p) {
                    float v0, v1; unpack2(acc[p], v0, v1);
                    v0 += bL[2 * p];  v1 += bL[2 * p + 1];
                    m |= (u64)(v0 > 0.0f) << (2 * p);
                    m |= (u64)(v1 > 0.0f) << (2 * p + 1);
                    scp[p * 256 + tid] = pack2(fmaxf(v0, 0.0f), fmaxf(v1, 0.0f));
                }
                if (layer == 0) m0 = m; else m1 = m;
            }
        }

        // ---- VJP (values only; fast tree dots) ----
        u64 v[32];
        {
            const ulonglong2* er = reinterpret_cast<const ulonglong2*>(e + row * 64);
#pragma unroll
            for (int i = 0; i < 16; ++i) { ulonglong2 q = er[i]; v[2*i] = q.x; v[2*i+1] = q.y; }
        }

        // a1 = (W2'^T e) .* m1
#pragma unroll 2
        for (int k2 = 0; k2 < 32; ++k2) {
            float d0 = dot64(Wb + 2 * 4096 + (2 * k2) * 64, v);
            float d1 = dot64(Wb + 2 * 4096 + (2 * k2 + 1) * 64, v);
            d0 = ((m1 >> (2 * k2)) & 1ull) ? d0 : 0.0f;
            d1 = ((m1 >> (2 * k2 + 1)) & 1ull) ? d1 : 0.0f;
            scp[k2 * 256 + tid] = pack2(d0, d1);
        }
#pragma unroll
        for (int m = 0; m < 32; ++m) v[m] = scp[m * 256 + tid];

        // a0 = (W1'^T a1) .* m0
#pragma unroll 2
        for (int k2 = 0; k2 < 32; ++k2) {
            float d0 = dot64(Wb + 1 * 4096 + (2 * k2) * 64, v);
            float d1 = dot64(Wb + 1 * 4096 + (2 * k2 + 1) * 64, v);
            d0 = ((m0 >> (2 * k2)) & 1ull) ? d0 : 0.0f;
            d1 = ((m0 >> (2 * k2 + 1)) & 1ull) ? d1 : 0.0f;
            scp[k2 * 256 + tid] = pack2(d0, d1);
        }
#pragma unroll
        for (int m = 0; m < 32; ++m) v[m] = scp[m * 256 + tid];

        // e_dfdz = W0'^T a0 ; div = dot(e_dfdz, e) fused
        {
            u64 e2[32];
            const ulonglong2* er = reinterpret_cast<const ulonglong2*>(e + row * 64);
#pragma unroll
            for (int i = 0; i < 16; ++i) { ulonglong2 q = er[i]; e2[2*i] = q.x; e2[2*i+1] = q.y; }

            u64 divA = 0ull, divB = 0ull;
#pragma unroll 2
            for (int k2 = 0; k2 < 32; ++k2) {
                float d0 = dot64(Wb + 0 * 4096 + (2 * k2) * 64, v);
                float d1 = dot64(Wb + 0 * 4096 + (2 * k2 + 1) * 64, v);
                u64 dd = pack2(d0, d1);
                if (k2 & 1) divB = ffma2(dd, e2[k2], divB);
                else        divA = ffma2(dd, e2[k2], divA);
            }
            out[(long)NB * 64 + row] = -hsum2(fadd2(divA, divB));
        }
    }
}

extern "C" void kernel_launch(void* const* d_in, const int* in_sizes, int n_in,
                              void* d_out, int out_size) {
    const float* t  = (const float*)d_in[0];
    const float* z  = (const float*)d_in[1];
    const float* e  = (const float*)d_in[2];
    const float* W0 = (const float*)d_in[3];
    const float* b0 = (const float*)d_in[4];
    const float* W1 = (const float*)d_in[5];
    const float* b1 = (const float*)d_in[6];
    const float* W2 = (const float*)d_in[7];
    const float* b2 = (const float*)d_in[8];
    float* out = (float*)d_out;

    cudaFuncSetAttribute(odefunc_kernel,
                         cudaFuncAttributeMaxDynamicSharedMemorySize, SMEM_BYTES);

    odefunc_kernel<<<GRID_X, THREADS, SMEM_BYTES>>>(t, z, e, W0, b0, W1, b1, W2, b2, out);
}